// round 1
// baseline (speedup 1.0000x reference)
#include <cuda_runtime.h>

// SpatialGNN: 2-layer GATv2 over G = B*K*L = 6144 independent graphs,
// N=32 nodes, C=64 channels, H=4 heads, D=16, E=160 edges (shared topology).
// Fully fused: one block processes NG=4 graphs (same b,k; consecutive l) with
// everything resident in shared memory.

#define Bb 16
#define Cc 64
#define Nn 32
#define Kk 16
#define Ll 24
#define Ee 160
#define Hh 4
#define Dd 16
#define NG 4
#define HP 65        // padded row stride (floats) for node-feature tiles
#define WP 72        // padded row stride (floats) for transposed weights (mult of 4 for LDS.128)
#define NTHREADS 512

struct Smem {
    float h [NG][Nn * HP];
    float xl[NG][Nn * HP];
    float xr[NG][Nn * HP];
    float Wls[64 * WP];     // Wl transposed: Wls[ci*WP + co]
    float Wrs[64 * WP];
    float sc[NG][Ee][Hh];   // edge scores -> exp(score - max) in place
    float rden[NG][Nn][Hh]; // 1/denominator per (graph, dst node, head)
    float bl[Cc], br[Cc], Wes[Cc], atts[Cc], bos[Cc];
    float ew[Ee];
    int   srcs[Ee], dsts[Ee];
    int   deg[Nn], off[Nn], csr[Ee];
};

__global__ void __launch_bounds__(NTHREADS, 1)
gat_fused(const float* __restrict__ x, const int* __restrict__ ei,
          const float* __restrict__ ewg,
          const float* __restrict__ Wl, const float* __restrict__ blg,
          const float* __restrict__ Wr, const float* __restrict__ brg,
          const float* __restrict__ Weg, const float* __restrict__ attg,
          const float* __restrict__ bog, float* __restrict__ out)
{
    extern __shared__ char smem_raw[];
    Smem* s = reinterpret_cast<Smem*>(smem_raw);
    const int tid = threadIdx.x;
    const int bk = blockIdx.x / (Ll / NG);
    const int lg = blockIdx.x % (Ll / NG);
    const int b  = bk >> 4;
    const int k  = bk & 15;
    const int l0 = lg * NG;

    // ---- load h for 4 graphs: h[l'][n][c] = x[b,c,n,k,l0+l'] (float4 along l) ----
    const float* xb = x + ((size_t)b * Cc * Nn) * (Kk * Ll) + (size_t)k * Ll + l0;
    for (int i2 = tid; i2 < Cc * Nn; i2 += NTHREADS) {
        int c = i2 >> 5, n = i2 & 31;
        float4 v = *reinterpret_cast<const float4*>(xb + ((size_t)c * Nn + n) * (Kk * Ll));
        int o = n * HP + c;
        s->h[0][o] = v.x; s->h[1][o] = v.y; s->h[2][o] = v.z; s->h[3][o] = v.w;
    }

    // ---- topology: deterministic per-dst CSR ----
    for (int e = tid; e < Ee; e += NTHREADS) {
        s->srcs[e] = ei[e];
        s->dsts[e] = ei[Ee + e];
        s->ew[e]   = ewg[e];
    }
    __syncthreads();
    if (tid < Nn) {
        int n = tid, cnt = 0;
        for (int e = 0; e < Ee; e++) cnt += (s->dsts[e] == n);
        s->deg[n] = cnt;
    }
    __syncthreads();
    if (tid == 0) {
        int a = 0;
        for (int n = 0; n < Nn; n++) { s->off[n] = a; a += s->deg[n]; }
    }
    __syncthreads();
    if (tid < Nn) {
        int n = tid, p = s->off[n];
        for (int e = 0; e < Ee; e++) if (s->dsts[e] == n) s->csr[p++] = e;
    }

    for (int layer = 0; layer < 2; layer++) {
        __syncthreads();   // h ready (initial load or prev agg); csr ready; prev phase done

        // ---- stage layer weights (transposed) ----
        const float* Wli = Wl + layer * Cc * Cc;
        const float* Wri = Wr + layer * Cc * Cc;
        for (int t = tid; t < Cc * Cc; t += NTHREADS) {
            int co = t >> 6, ci = t & 63;
            s->Wls[ci * WP + co] = Wli[t];
            s->Wrs[ci * WP + co] = Wri[t];
        }
        if (tid < Cc) {
            s->bl[tid]   = blg[layer * Cc + tid];
            s->br[tid]   = brg[layer * Cc + tid];
            s->Wes[tid]  = Weg[layer * Cc + tid];   // We[layer][c][0]
            s->atts[tid] = attg[layer * Cc + tid];  // att[layer][h][d] flattened
            s->bos[tid]  = bog[layer * Cc + tid];
        }
        __syncthreads();

        // ---- GEMM: xl = h @ Wl^T + bl (warps 0-7), xr = h @ Wr^T + br (warps 8-15) ----
        {
            const int half = tid >> 8;          // 0 -> xl, 1 -> xr
            const int t    = tid & 255;
            const int gp   = t >> 6;
            const int n0   = ((t >> 3) & 7) * 4;
            const int co0  = (t & 7) * 8;
            const float* W    = half ? s->Wrs : s->Wls;
            const float* bias = half ? s->br  : s->bl;
            float* dst        = half ? s->xr[gp] : s->xl[gp];
            const float* hh   = s->h[gp];

            float acc[4][8];
            #pragma unroll
            for (int r = 0; r < 4; r++)
                #pragma unroll
                for (int j = 0; j < 8; j++) acc[r][j] = bias[co0 + j];

            #pragma unroll 4
            for (int ci = 0; ci < Cc; ci++) {
                float4 w0 = *reinterpret_cast<const float4*>(W + ci * WP + co0);
                float4 w1 = *reinterpret_cast<const float4*>(W + ci * WP + co0 + 4);
                float wv[8] = {w0.x, w0.y, w0.z, w0.w, w1.x, w1.y, w1.z, w1.w};
                #pragma unroll
                for (int r = 0; r < 4; r++) {
                    float hv = hh[(n0 + r) * HP + ci];
                    #pragma unroll
                    for (int j = 0; j < 8; j++) acc[r][j] = fmaf(hv, wv[j], acc[r][j]);
                }
            }
            #pragma unroll
            for (int r = 0; r < 4; r++)
                #pragma unroll
                for (int j = 0; j < 8; j++)
                    dst[(n0 + r) * HP + co0 + j] = acc[r][j];
        }
        __syncthreads();

        // ---- edge scores: score[g,e,h] = sum_d lrelu(xl[src]+xr[dst]+ew*We) * att ----
        for (int t = tid; t < NG * Ee * Hh; t += NTHREADS) {
            int gp = t / (Ee * Hh);
            int r  = t - gp * (Ee * Hh);
            int e  = r >> 2, hd = r & 3;
            const float* xs = &s->xl[gp][s->srcs[e] * HP + hd * Dd];
            const float* xd = &s->xr[gp][s->dsts[e] * HP + hd * Dd];
            float w = s->ew[e];
            float sum = 0.f;
            #pragma unroll
            for (int d = 0; d < Dd; d++) {
                float z = xs[d] + xd[d] + w * s->Wes[hd * Dd + d];
                z = (z > 0.f) ? z : 0.2f * z;
                sum += z * s->atts[hd * Dd + d];
            }
            s->sc[gp][e][hd] = sum;
        }
        __syncthreads();

        // ---- segment softmax over incoming edges: exp in place, store 1/denom ----
        {
            int gp = tid >> 7;
            int r  = tid & 127;
            int n  = r >> 2, hd = r & 3;
            int dg = s->deg[n], o = s->off[n];
            float m = -1e30f;
            for (int j = 0; j < dg; j++)
                m = fmaxf(m, s->sc[gp][s->csr[o + j]][hd]);
            float den = 0.f;
            for (int j = 0; j < dg; j++) {
                int e = s->csr[o + j];
                float ex = __expf(s->sc[gp][e][hd] - m);
                s->sc[gp][e][hd] = ex;
                den += ex;
            }
            s->rden[gp][n][hd] = (dg > 0) ? (1.f / den) : 0.f;
        }
        __syncthreads();

        // ---- aggregate: h_next[n,c] = (sum_e ex * xl[src,c]) * rden + bias ( + relu) ----
        for (int t = tid; t < NG * Nn * Cc; t += NTHREADS) {
            int gp = t >> 11;
            int r  = t & 2047;
            int n  = r >> 6, c = r & 63;
            int hd = c >> 4;
            int dg = s->deg[n], o = s->off[n];
            float a = 0.f;
            for (int j = 0; j < dg; j++) {
                int e = s->csr[o + j];
                a += s->sc[gp][e][hd] * s->xl[gp][s->srcs[e] * HP + c];
            }
            a = a * s->rden[gp][n][hd] + s->bos[c];
            if (layer == 0) a = fmaxf(a, 0.f);
            s->h[gp][n * HP + c] = a;
        }
    }
    __syncthreads();

    // ---- write output: out[b,c,n,k,l0..l0+3] = h[l'][n][c] (float4 along l) ----
    float* ob = out + ((size_t)b * Cc * Nn) * (Kk * Ll) + (size_t)k * Ll + l0;
    for (int i2 = tid; i2 < Cc * Nn; i2 += NTHREADS) {
        int c = i2 >> 5, n = i2 & 31;
        int o = n * HP + c;
        float4 v = make_float4(s->h[0][o], s->h[1][o], s->h[2][o], s->h[3][o]);
        *reinterpret_cast<float4*>(ob + ((size_t)c * Nn + n) * (Kk * Ll)) = v;
    }
}

extern "C" void kernel_launch(void* const* d_in, const int* in_sizes, int n_in,
                              void* d_out, int out_size)
{
    const float* x   = (const float*)d_in[0];
    const int*   ei  = (const int*)  d_in[1];
    const float* ewg = (const float*)d_in[2];
    const float* Wl  = (const float*)d_in[3];
    const float* bl  = (const float*)d_in[4];
    const float* Wr  = (const float*)d_in[5];
    const float* br  = (const float*)d_in[6];
    const float* We  = (const float*)d_in[7];
    const float* att = (const float*)d_in[8];
    const float* bo  = (const float*)d_in[9];
    float* out = (float*)d_out;

    (void)in_sizes; (void)n_in; (void)out_size;

    int smem = (int)sizeof(Smem);
    cudaFuncSetAttribute(gat_fused, cudaFuncAttributeMaxDynamicSharedMemorySize, smem);

    dim3 grid(Bb * Kk * (Ll / NG));   // 1536 blocks, 4 graphs each
    gat_fused<<<grid, NTHREADS, smem>>>(x, ei, ewg, Wl, bl, Wr, br, We, att, bo, out);
}

// round 2
// speedup vs baseline: 1.2385x; 1.2385x over previous
#include <cuda_runtime.h>

// SpatialGNN: 2-layer GATv2 over G = B*K*L = 6144 independent graphs,
// N=32 nodes, C=64 channels, H=4 heads, D=16, E=160 edges (shared topology).
// Fused; one block = NG=2 graphs; 2 blocks/SM (smem ~96KB, regs capped at 64).
// h stored transposed (hT[ci][n]) so the GEMM does 2x LDS.128 per 16 FMA.

#define Bb 16
#define Cc 64
#define Nn 32
#define Kk 16
#define Ll 24
#define Ee 160
#define Hh 4
#define Dd 16
#define NG 2
#define NP 36        // hT row stride (floats): hT[ci*NP + n], mult of 4
#define XP 68        // xl/xr row stride (floats): x[n*XP + c], mult of 4
#define WP 68        // transposed-weight row stride: W[ci*WP + co], mult of 4
#define NTHREADS 512

struct __align__(16) Smem {
    float hT[NG][Cc * NP];     // input features, ci-major
    float xl[NG][Nn * XP];
    float xr[NG][Nn * XP];
    float Wls[Cc * WP];        // Wl transposed: [ci][co]
    float Wrs[Cc * WP];
    float sc[NG][Ee][Hh];      // scores -> exp(score - max) in place
    float rden[NG][Nn][Hh];
    float bl[Cc], br[Cc];
    float Wes[Cc] __attribute__((aligned(16)));
    float atts[Cc] __attribute__((aligned(16)));
    float bos[Cc];
    float ew[Ee];
    int   srcs[Ee], dsts[Ee];
    int   deg[Nn], off[Nn], csr[Ee];
};

__global__ void __launch_bounds__(NTHREADS, 2)
gat_fused(const float* __restrict__ x, const int* __restrict__ ei,
          const float* __restrict__ ewg,
          const float* __restrict__ Wl, const float* __restrict__ blg,
          const float* __restrict__ Wr, const float* __restrict__ brg,
          const float* __restrict__ Weg, const float* __restrict__ attg,
          const float* __restrict__ bog, float* __restrict__ out)
{
    extern __shared__ char smem_raw[];
    Smem* s = reinterpret_cast<Smem*>(smem_raw);
    const int tid = threadIdx.x;
    const int bk = blockIdx.x / (Ll / NG);
    const int lg = blockIdx.x % (Ll / NG);
    const int b  = bk >> 4;
    const int k  = bk & 15;
    const int l0 = lg * NG;

    // ---- load h for NG graphs: hT[l'][ci*NP+n] = x[b,ci,n,k,l0+l'] ----
    const float* xb = x + ((size_t)b * Cc * Nn) * (Kk * Ll) + (size_t)k * Ll + l0;
    for (int i2 = tid; i2 < Cc * Nn; i2 += NTHREADS) {
        int c = i2 >> 5, n = i2 & 31;
        float2 v = *reinterpret_cast<const float2*>(xb + ((size_t)c * Nn + n) * (Kk * Ll));
        int o = c * NP + n;
        s->hT[0][o] = v.x; s->hT[1][o] = v.y;
    }

    // ---- topology: deterministic per-dst CSR ----
    for (int e = tid; e < Ee; e += NTHREADS) {
        s->srcs[e] = ei[e];
        s->dsts[e] = ei[Ee + e];
        s->ew[e]   = ewg[e];
    }
    __syncthreads();
    if (tid < Nn) {
        int n = tid, cnt = 0;
        for (int e = 0; e < Ee; e++) cnt += (s->dsts[e] == n);
        s->deg[n] = cnt;
    }
    __syncthreads();
    if (tid == 0) {
        int a = 0;
        for (int n = 0; n < Nn; n++) { s->off[n] = a; a += s->deg[n]; }
    }
    __syncthreads();
    if (tid < Nn) {
        int n = tid, p = s->off[n];
        for (int e = 0; e < Ee; e++) if (s->dsts[e] == n) s->csr[p++] = e;
    }

    for (int layer = 0; layer < 2; layer++) {
        __syncthreads();

        // ---- stage layer weights (transposed) + per-layer vectors ----
        const float* Wli = Wl + layer * Cc * Cc;
        const float* Wri = Wr + layer * Cc * Cc;
        for (int t = tid; t < Cc * Cc; t += NTHREADS) {
            int co = t >> 6, ci = t & 63;
            s->Wls[ci * WP + co] = Wli[t];
            s->Wrs[ci * WP + co] = Wri[t];
        }
        if (tid < Cc) {
            s->bl[tid]   = blg[layer * Cc + tid];
            s->br[tid]   = brg[layer * Cc + tid];
            s->Wes[tid]  = Weg[layer * Cc + tid];
            s->atts[tid] = attg[layer * Cc + tid];
            s->bos[tid]  = bog[layer * Cc + tid];
        }
        __syncthreads();

        // ---- GEMM: 512 threads; tile = 4 nodes x 4 out-channels per thread ----
        // half: 0 -> xl = h@Wl^T+bl, 1 -> xr = h@Wr^T+br
        {
            const int half = tid >> 8;
            const int t    = tid & 255;
            const int gp   = t >> 7;
            const int t2   = t & 127;
            const int n0   = ((t2 >> 4) & 7) * 4;
            const int co0  = (t2 & 15) * 4;
            const float* W    = half ? s->Wrs : s->Wls;
            const float* bias = half ? s->br  : s->bl;
            float* dst        = half ? s->xr[gp] : s->xl[gp];
            const float* hh   = s->hT[gp];

            float acc[4][4];
            {
                float4 bv = *reinterpret_cast<const float4*>(bias + co0);
                #pragma unroll
                for (int r = 0; r < 4; r++) {
                    acc[r][0] = bv.x; acc[r][1] = bv.y; acc[r][2] = bv.z; acc[r][3] = bv.w;
                }
            }
            #pragma unroll 4
            for (int ci = 0; ci < Cc; ci++) {
                float4 wv = *reinterpret_cast<const float4*>(W  + ci * WP + co0);
                float4 hv = *reinterpret_cast<const float4*>(hh + ci * NP + n0);
                float hr[4] = {hv.x, hv.y, hv.z, hv.w};
                float wc[4] = {wv.x, wv.y, wv.z, wv.w};
                #pragma unroll
                for (int r = 0; r < 4; r++)
                    #pragma unroll
                    for (int j = 0; j < 4; j++)
                        acc[r][j] = fmaf(hr[r], wc[j], acc[r][j]);
            }
            #pragma unroll
            for (int r = 0; r < 4; r++) {
                float4 o4 = make_float4(acc[r][0], acc[r][1], acc[r][2], acc[r][3]);
                *reinterpret_cast<float4*>(dst + (n0 + r) * XP + co0) = o4;
            }
        }
        __syncthreads();

        // ---- edge scores (vectorized over D with float4) ----
        for (int t = tid; t < NG * Ee * Hh; t += NTHREADS) {
            int gp = t / (Ee * Hh);
            int r  = t - gp * (Ee * Hh);
            int e  = r >> 2, hd = r & 3;
            const float4* xs4 = reinterpret_cast<const float4*>(&s->xl[gp][s->srcs[e] * XP + hd * Dd]);
            const float4* xd4 = reinterpret_cast<const float4*>(&s->xr[gp][s->dsts[e] * XP + hd * Dd]);
            const float4* we4 = reinterpret_cast<const float4*>(&s->Wes[hd * Dd]);
            const float4* at4 = reinterpret_cast<const float4*>(&s->atts[hd * Dd]);
            float w = s->ew[e];
            float sum = 0.f;
            #pragma unroll
            for (int q = 0; q < 4; q++) {
                float4 a = xs4[q], bq = xd4[q], wq = we4[q], tq = at4[q];
                float z;
                z = a.x + bq.x + w * wq.x; z = (z > 0.f) ? z : 0.2f * z; sum += z * tq.x;
                z = a.y + bq.y + w * wq.y; z = (z > 0.f) ? z : 0.2f * z; sum += z * tq.y;
                z = a.z + bq.z + w * wq.z; z = (z > 0.f) ? z : 0.2f * z; sum += z * tq.z;
                z = a.w + bq.w + w * wq.w; z = (z > 0.f) ? z : 0.2f * z; sum += z * tq.w;
            }
            s->sc[gp][e][hd] = sum;
        }
        __syncthreads();

        // ---- segment softmax: exp in place, 1/denom per (gp, n, head) ----
        if (tid < NG * Nn * Hh) {
            int gp = tid / (Nn * Hh);
            int r  = tid - gp * (Nn * Hh);
            int n  = r >> 2, hd = r & 3;
            int dg = s->deg[n], o = s->off[n];
            float m = -1e30f;
            for (int j = 0; j < dg; j++)
                m = fmaxf(m, s->sc[gp][s->csr[o + j]][hd]);
            float den = 0.f;
            for (int j = 0; j < dg; j++) {
                int e = s->csr[o + j];
                float ex = __expf(s->sc[gp][e][hd] - m);
                s->sc[gp][e][hd] = ex;
                den += ex;
            }
            s->rden[gp][n][hd] = (dg > 0) ? (1.f / den) : 0.f;
        }
        __syncthreads();

        // ---- aggregate into hT (next layer's input layout) ----
        for (int t = tid; t < NG * Nn * Cc; t += NTHREADS) {
            int gp = t >> 11;
            int r  = t & 2047;
            int n  = r >> 6, c = r & 63;
            int hd = c >> 4;
            int dg = s->deg[n], o = s->off[n];
            float a = 0.f;
            for (int j = 0; j < dg; j++) {
                int e = s->csr[o + j];
                a += s->sc[gp][e][hd] * s->xl[gp][s->srcs[e] * XP + c];
            }
            a = a * s->rden[gp][n][hd] + s->bos[c];
            if (layer == 0) a = fmaxf(a, 0.f);
            s->hT[gp][c * NP + n] = a;
        }
    }
    __syncthreads();

    // ---- write output: out[b,c,n,k,l0+l'] = hT[l'][c*NP+n] ----
    float* ob = out + ((size_t)b * Cc * Nn) * (Kk * Ll) + (size_t)k * Ll + l0;
    for (int i2 = tid; i2 < Cc * Nn; i2 += NTHREADS) {
        int c = i2 >> 5, n = i2 & 31;
        int o = c * NP + n;
        float2 v = make_float2(s->hT[0][o], s->hT[1][o]);
        *reinterpret_cast<float2*>(ob + ((size_t)c * Nn + n) * (Kk * Ll)) = v;
    }
}

extern "C" void kernel_launch(void* const* d_in, const int* in_sizes, int n_in,
                              void* d_out, int out_size)
{
    const float* x   = (const float*)d_in[0];
    const int*   ei  = (const int*)  d_in[1];
    const float* ewg = (const float*)d_in[2];
    const float* Wl  = (const float*)d_in[3];
    const float* bl  = (const float*)d_in[4];
    const float* Wr  = (const float*)d_in[5];
    const float* br  = (const float*)d_in[6];
    const float* We  = (const float*)d_in[7];
    const float* att = (const float*)d_in[8];
    const float* bo  = (const float*)d_in[9];
    float* out = (float*)d_out;

    (void)in_sizes; (void)n_in; (void)out_size;

    int smem = (int)sizeof(Smem);
    cudaFuncSetAttribute(gat_fused, cudaFuncAttributeMaxDynamicSharedMemorySize, smem);

    dim3 grid(Bb * Kk * (Ll / NG));   // 3072 blocks, 2 graphs each
    gat_fused<<<grid, NTHREADS, smem>>>(x, ei, ewg, Wl, bl, Wr, br, We, att, bo, out);
}

// round 3
// speedup vs baseline: 1.2968x; 1.0471x over previous
#include <cuda_runtime.h>

// SpatialGNN: 2-layer GATv2 over G = B*K*L = 6144 graphs, N=32, C=64, H=4,
// D=16, E=160 shared edges. Fused; one block = NG=2 graphs; 2 blocks/SM.
// R3: GEMM warp remap (4n x 8co per warp -> 2 smem wavefronts/ci) and
// edge-score phase restructured per (dst,head,d-half) with xr cached in regs.

#define Bb 16
#define Cc 64
#define Nn 32
#define Kk 16
#define Ll 24
#define Ee 160
#define Hh 4
#define Dd 16
#define NG 2
#define NP 36        // hT row stride (floats)
#define XP 68        // xl/xr row stride (floats)
#define WP 68        // transposed-weight row stride (floats)
#define NTHREADS 512

struct __align__(16) Smem {
    float hT[NG][Cc * NP];     // input features, ci-major
    float xl[NG][Nn * XP];
    float xr[NG][Nn * XP];
    float Wls[Cc * WP];        // Wl transposed: [ci][co]
    float Wrs[Cc * WP];
    float sc[NG][Ee][2 * Hh];  // per-half partial scores; exp lands in slot h*2
    float rden[NG][Nn][Hh];
    float bl[Cc], br[Cc];
    float Wes[Cc] __attribute__((aligned(16)));
    float atts[Cc] __attribute__((aligned(16)));
    float bos[Cc];
    float ew[Ee];
    int   srcs[Ee], dsts[Ee];
    int   deg[Nn], off[Nn], csr[Ee];
};

__global__ void __launch_bounds__(NTHREADS, 2)
gat_fused(const float* __restrict__ x, const int* __restrict__ ei,
          const float* __restrict__ ewg,
          const float* __restrict__ Wl, const float* __restrict__ blg,
          const float* __restrict__ Wr, const float* __restrict__ brg,
          const float* __restrict__ Weg, const float* __restrict__ attg,
          const float* __restrict__ bog, float* __restrict__ out)
{
    extern __shared__ char smem_raw[];
    Smem* s = reinterpret_cast<Smem*>(smem_raw);
    const int tid = threadIdx.x;
    const int bk = blockIdx.x / (Ll / NG);
    const int lg = blockIdx.x % (Ll / NG);
    const int b  = bk >> 4;
    const int k  = bk & 15;
    const int l0 = lg * NG;

    // ---- load h: hT[l'][ci*NP+n] = x[b,ci,n,k,l0+l'] ----
    const float* xb = x + ((size_t)b * Cc * Nn) * (Kk * Ll) + (size_t)k * Ll + l0;
    for (int i2 = tid; i2 < Cc * Nn; i2 += NTHREADS) {
        int c = i2 >> 5, n = i2 & 31;
        float2 v = *reinterpret_cast<const float2*>(xb + ((size_t)c * Nn + n) * (Kk * Ll));
        int o = c * NP + n;
        s->hT[0][o] = v.x; s->hT[1][o] = v.y;
    }

    // ---- topology: deterministic per-dst CSR ----
    for (int e = tid; e < Ee; e += NTHREADS) {
        s->srcs[e] = ei[e];
        s->dsts[e] = ei[Ee + e];
        s->ew[e]   = ewg[e];
    }
    __syncthreads();
    if (tid < Nn) {
        int n = tid, cnt = 0;
        for (int e = 0; e < Ee; e++) cnt += (s->dsts[e] == n);
        s->deg[n] = cnt;
    }
    __syncthreads();
    if (tid == 0) {
        int a = 0;
        for (int n = 0; n < Nn; n++) { s->off[n] = a; a += s->deg[n]; }
    }
    __syncthreads();
    if (tid < Nn) {
        int n = tid, p = s->off[n];
        for (int e = 0; e < Ee; e++) if (s->dsts[e] == n) s->csr[p++] = e;
    }

    for (int layer = 0; layer < 2; layer++) {
        __syncthreads();

        // ---- stage layer weights (transposed) + per-layer vectors ----
        const float* Wli = Wl + layer * Cc * Cc;
        const float* Wri = Wr + layer * Cc * Cc;
        for (int t = tid; t < Cc * Cc; t += NTHREADS) {
            int co = t >> 6, ci = t & 63;
            s->Wls[ci * WP + co] = Wli[t];
            s->Wrs[ci * WP + co] = Wri[t];
        }
        if (tid < Cc) {
            s->bl[tid]   = blg[layer * Cc + tid];
            s->br[tid]   = brg[layer * Cc + tid];
            s->Wes[tid]  = Weg[layer * Cc + tid];
            s->atts[tid] = attg[layer * Cc + tid];
            s->bos[tid]  = bog[layer * Cc + tid];
        }
        __syncthreads();

        // ---- GEMM: per thread 4 nodes x 4 out-ch; warp = 4n-groups x 8co-groups
        //      so operand fetches are contiguous: h 64B (1 wf) + W 128B (1 wf) per ci.
        {
            const int half = tid >> 8;          // 0 -> xl, 1 -> xr
            const int gp   = (tid >> 7) & 1;
            const int t2   = tid & 127;
            const int lane = t2 & 31;
            const int wq   = t2 >> 5;
            const int n0   = (lane & 3) * 4 + (wq & 1) * 16;
            const int co0  = (lane >> 2) * 4 + (wq >> 1) * 32;
            const float* W    = half ? s->Wrs : s->Wls;
            const float* bias = half ? s->br  : s->bl;
            float* dst        = half ? s->xr[gp] : s->xl[gp];
            const float* hh   = s->hT[gp];

            float acc[4][4];
            {
                float4 bv = *reinterpret_cast<const float4*>(bias + co0);
                #pragma unroll
                for (int r = 0; r < 4; r++) {
                    acc[r][0] = bv.x; acc[r][1] = bv.y; acc[r][2] = bv.z; acc[r][3] = bv.w;
                }
            }
            #pragma unroll 8
            for (int ci = 0; ci < Cc; ci++) {
                float4 wv = *reinterpret_cast<const float4*>(W  + ci * WP + co0);
                float4 hv = *reinterpret_cast<const float4*>(hh + ci * NP + n0);
                float hr[4] = {hv.x, hv.y, hv.z, hv.w};
                float wc[4] = {wv.x, wv.y, wv.z, wv.w};
                #pragma unroll
                for (int r = 0; r < 4; r++)
                    #pragma unroll
                    for (int j = 0; j < 4; j++)
                        acc[r][j] = fmaf(hr[r], wc[j], acc[r][j]);
            }
            #pragma unroll
            for (int r = 0; r < 4; r++) {
                float4 o4 = make_float4(acc[r][0], acc[r][1], acc[r][2], acc[r][3]);
                *reinterpret_cast<float4*>(dst + (n0 + r) * XP + co0) = o4;
            }
        }
        __syncthreads();

        // ---- edge scores, per (gp, dst n, head, d-half): xr row cached in regs;
        //      per incoming edge only xl[src] is fetched (64B). Partial dot per half.
        {
            const int hf = tid & 1;
            const int hd = (tid >> 1) & 3;
            const int n  = (tid >> 3) & 31;
            const int gp = tid >> 8;
            const int base = hd * Dd + hf * 8;
            float4 we0 = *reinterpret_cast<const float4*>(&s->Wes[base]);
            float4 we1 = *reinterpret_cast<const float4*>(&s->Wes[base + 4]);
            float4 at0 = *reinterpret_cast<const float4*>(&s->atts[base]);
            float4 at1 = *reinterpret_cast<const float4*>(&s->atts[base + 4]);
            float4 xr0 = *reinterpret_cast<const float4*>(&s->xr[gp][n * XP + base]);
            float4 xr1 = *reinterpret_cast<const float4*>(&s->xr[gp][n * XP + base + 4]);
            int dg = s->deg[n], o = s->off[n];
            for (int j = 0; j < dg; j++) {
                int e  = s->csr[o + j];
                int sr = s->srcs[e];
                float w = s->ew[e];
                float4 a0 = *reinterpret_cast<const float4*>(&s->xl[gp][sr * XP + base]);
                float4 a1 = *reinterpret_cast<const float4*>(&s->xl[gp][sr * XP + base + 4]);
                float z, sum = 0.f;
                z = a0.x + xr0.x + w * we0.x; z = (z > 0.f) ? z : 0.2f * z; sum += z * at0.x;
                z = a0.y + xr0.y + w * we0.y; z = (z > 0.f) ? z : 0.2f * z; sum += z * at0.y;
                z = a0.z + xr0.z + w * we0.z; z = (z > 0.f) ? z : 0.2f * z; sum += z * at0.z;
                z = a0.w + xr0.w + w * we0.w; z = (z > 0.f) ? z : 0.2f * z; sum += z * at0.w;
                z = a1.x + xr1.x + w * we1.x; z = (z > 0.f) ? z : 0.2f * z; sum += z * at1.x;
                z = a1.y + xr1.y + w * we1.y; z = (z > 0.f) ? z : 0.2f * z; sum += z * at1.y;
                z = a1.z + xr1.z + w * we1.z; z = (z > 0.f) ? z : 0.2f * z; sum += z * at1.z;
                z = a1.w + xr1.w + w * we1.w; z = (z > 0.f) ? z : 0.2f * z; sum += z * at1.w;
                s->sc[gp][e][hd * 2 + hf] = sum;
            }
        }
        __syncthreads();

        // ---- segment softmax per (gp, n, head): sum halves, exp in place (slot 0) ----
        if (tid < NG * Nn * Hh) {
            int gp = tid >> 7;
            int r  = tid & 127;
            int n  = r >> 2, hd = r & 3;
            int dg = s->deg[n], o = s->off[n];
            float m = -1e30f;
            for (int j = 0; j < dg; j++) {
                int e = s->csr[o + j];
                float2 p = *reinterpret_cast<const float2*>(&s->sc[gp][e][hd * 2]);
                m = fmaxf(m, p.x + p.y);
            }
            float den = 0.f;
            for (int j = 0; j < dg; j++) {
                int e = s->csr[o + j];
                float2 p = *reinterpret_cast<const float2*>(&s->sc[gp][e][hd * 2]);
                float ex = __expf(p.x + p.y - m);
                s->sc[gp][e][hd * 2] = ex;
                den += ex;
            }
            s->rden[gp][n][hd] = (dg > 0) ? (1.f / den) : 0.f;
        }
        __syncthreads();

        // ---- aggregate into hT (next layer's input layout) ----
        for (int t = tid; t < NG * Nn * Cc; t += NTHREADS) {
            int gp = t >> 11;
            int r  = t & 2047;
            int n  = r >> 6, c = r & 63;
            int hd2 = (c >> 4) << 1;
            int dg = s->deg[n], o = s->off[n];
            float a = 0.f;
            for (int j = 0; j < dg; j++) {
                int e = s->csr[o + j];
                a += s->sc[gp][e][hd2] * s->xl[gp][s->srcs[e] * XP + c];
            }
            a = a * s->rden[gp][n][hd2 >> 1] + s->bos[c];
            if (layer == 0) a = fmaxf(a, 0.f);
            s->hT[gp][c * NP + n] = a;
        }
    }
    __syncthreads();

    // ---- write output: out[b,c,n,k,l0+l'] = hT[l'][c*NP+n] ----
    float* ob = out + ((size_t)b * Cc * Nn) * (Kk * Ll) + (size_t)k * Ll + l0;
    for (int i2 = tid; i2 < Cc * Nn; i2 += NTHREADS) {
        int c = i2 >> 5, n = i2 & 31;
        int o = c * NP + n;
        float2 v = make_float2(s->hT[0][o], s->hT[1][o]);
        *reinterpret_cast<float2*>(ob + ((size_t)c * Nn + n) * (Kk * Ll)) = v;
    }
}

extern "C" void kernel_launch(void* const* d_in, const int* in_sizes, int n_in,
                              void* d_out, int out_size)
{
    const float* x   = (const float*)d_in[0];
    const int*   ei  = (const int*)  d_in[1];
    const float* ewg = (const float*)d_in[2];
    const float* Wl  = (const float*)d_in[3];
    const float* bl  = (const float*)d_in[4];
    const float* Wr  = (const float*)d_in[5];
    const float* br  = (const float*)d_in[6];
    const float* We  = (const float*)d_in[7];
    const float* att = (const float*)d_in[8];
    const float* bo  = (const float*)d_in[9];
    float* out = (float*)d_out;

    (void)in_sizes; (void)n_in; (void)out_size;

    int smem = (int)sizeof(Smem);
    cudaFuncSetAttribute(gat_fused, cudaFuncAttributeMaxDynamicSharedMemorySize, smem);

    dim3 grid(Bb * Kk * (Ll / NG));   // 3072 blocks, 2 graphs each
    gat_fused<<<grid, NTHREADS, smem>>>(x, ei, ewg, Wl, bl, Wr, br, We, att, bo, out);
}

// round 4
// speedup vs baseline: 1.4498x; 1.1180x over previous
#include <cuda_runtime.h>
#include <cuda_bf16.h>

// SpatialGNN: 2-layer GATv2 over G = 6144 graphs, N=32, C=64, H=4, D=16,
// E=160 shared edges. Fused; one block = 2 graphs; 2 blocks/SM.
// R4: GEMM on tensor cores via mma.m16n8k16 bf16 with hi/lo split
// (hi*Whi + hi*Wlo + lo*Whi) for ~fp32 accuracy.

#define Bb 16
#define Cc 64
#define Nn 32
#define Kk 16
#define Ll 24
#define Ee 160
#define Hh 4
#define Dd 16
#define NG 2
#define Mm 64         // GEMM rows = NG * Nn
#define KP 72         // bf16 row stride for hhi/hlo and weight tiles
#define XP 68         // fp32 row stride for xl/xr
#define OP 65         // fp32 row stride for hOut
#define NTHREADS 512

struct __align__(16) Smem {
    __nv_bfloat16 hhi[Mm * KP];          // h hi, row-major [row][ci]
    __nv_bfloat16 hlo[Mm * KP];          // h lo
    union {
        __nv_bfloat16 w[2][2][Cc * KP];  // [hi/lo][mat(l/r)][co*KP+ci] (col-major B)
        float hOut[NG][Nn * OP];         // final-layer fp32 result (aliased)
    };
    float xl[NG][Nn * XP];
    float xr[NG][Nn * XP];
    float sc[NG][Ee][2 * Hh];            // per-half partial scores; exp -> slot h*2
    float rden[NG][Nn][Hh];
    float bl[Cc], br[Cc];
    float Wes[Cc] __attribute__((aligned(16)));
    float atts[Cc] __attribute__((aligned(16)));
    float bos[Cc];
    float ew[Ee];
    int   srcs[Ee], dsts[Ee];
    int   deg[Nn], off[Nn], csr[Ee];
};

__device__ __forceinline__ void mma16816(float* d, const unsigned* a, const unsigned* b) {
    asm volatile(
        "mma.sync.aligned.m16n8k16.row.col.f32.bf16.bf16.f32 "
        "{%0,%1,%2,%3}, {%4,%5,%6,%7}, {%8,%9}, {%0,%1,%2,%3};"
        : "+f"(d[0]), "+f"(d[1]), "+f"(d[2]), "+f"(d[3])
        : "r"(a[0]), "r"(a[1]), "r"(a[2]), "r"(a[3]), "r"(b[0]), "r"(b[1]));
}

__global__ void __launch_bounds__(NTHREADS, 2)
gat_fused(const float* __restrict__ x, const int* __restrict__ ei,
          const float* __restrict__ ewg,
          const float* __restrict__ Wl, const float* __restrict__ blg,
          const float* __restrict__ Wr, const float* __restrict__ brg,
          const float* __restrict__ Weg, const float* __restrict__ attg,
          const float* __restrict__ bog, float* __restrict__ out)
{
    extern __shared__ char smem_raw[];
    Smem* s = reinterpret_cast<Smem*>(smem_raw);
    const int tid = threadIdx.x;
    const int bk = blockIdx.x / (Ll / NG);
    const int lg = blockIdx.x % (Ll / NG);
    const int b  = bk >> 4;
    const int k  = bk & 15;
    const int l0 = lg * NG;

    // ---- load h and convert to bf16 hi/lo: row = gp*32+n, col = c ----
    const float* xb = x + ((size_t)b * Cc * Nn) * (Kk * Ll) + (size_t)k * Ll + l0;
    for (int i2 = tid; i2 < Cc * Nn; i2 += NTHREADS) {
        int c = i2 >> 5, n = i2 & 31;
        float2 v = *reinterpret_cast<const float2*>(xb + ((size_t)c * Nn + n) * (Kk * Ll));
        float vv[2] = {v.x, v.y};
        #pragma unroll
        for (int gp = 0; gp < NG; gp++) {
            int o = (gp * Nn + n) * KP + c;
            __nv_bfloat16 hi = __float2bfloat16(vv[gp]);
            s->hhi[o] = hi;
            s->hlo[o] = __float2bfloat16(vv[gp] - __bfloat162float(hi));
        }
    }

    // ---- topology: deterministic per-dst CSR ----
    for (int e = tid; e < Ee; e += NTHREADS) {
        s->srcs[e] = ei[e];
        s->dsts[e] = ei[Ee + e];
        s->ew[e]   = ewg[e];
    }
    __syncthreads();
    if (tid < Nn) {
        int n = tid, cnt = 0;
        for (int e = 0; e < Ee; e++) cnt += (s->dsts[e] == n);
        s->deg[n] = cnt;
    }
    __syncthreads();
    if (tid == 0) {
        int a = 0;
        for (int n = 0; n < Nn; n++) { s->off[n] = a; a += s->deg[n]; }
    }
    __syncthreads();
    if (tid < Nn) {
        int n = tid, p = s->off[n];
        for (int e = 0; e < Ee; e++) if (s->dsts[e] == n) s->csr[p++] = e;
    }

    for (int layer = 0; layer < 2; layer++) {
        __syncthreads();

        // ---- stage weights (bf16 hi/lo, col-major: [co][ci]) + vectors ----
        const float* Wli = Wl + layer * Cc * Cc;
        const float* Wri = Wr + layer * Cc * Cc;
        for (int t = tid; t < 2 * Cc * Cc; t += NTHREADS) {
            int mat = t >> 12, co = (t >> 6) & 63, ci = t & 63;
            float wv = mat ? Wri[co * Cc + ci] : Wli[co * Cc + ci];
            __nv_bfloat16 hi = __float2bfloat16(wv);
            int o = co * KP + ci;
            s->w[0][mat][o] = hi;
            s->w[1][mat][o] = __float2bfloat16(wv - __bfloat162float(hi));
        }
        if (tid < Cc) {
            s->bl[tid]   = blg[layer * Cc + tid];
            s->br[tid]   = brg[layer * Cc + tid];
            s->Wes[tid]  = Weg[layer * Cc + tid];
            s->atts[tid] = attg[layer * Cc + tid];
            s->bos[tid]  = bog[layer * Cc + tid];
        }
        __syncthreads();

        // ---- tensor-core GEMM: warp w -> mat = w>>3, m16 tile mt, n32 half nh ----
        {
            const int w    = tid >> 5;
            const int lane = tid & 31;
            const int gID  = lane >> 2;        // group id 0..7
            const int tg   = lane & 3;         // thread in group
            const int mat  = w >> 3;           // 0 -> xl/Wl/bl, 1 -> xr/Wr/br
            const int mt   = (w >> 1) & 3;     // m-tile (16 rows)
            const int nh   = w & 1;            // n-half (32 cols)
            const int row0 = mt * 16 + gID;
            const __nv_bfloat16* Whi = s->w[0][mat];
            const __nv_bfloat16* Wlo = s->w[1][mat];
            const float* bias = mat ? s->br : s->bl;
            float* dst        = mat ? (float*)s->xr : (float*)s->xl;

            float acc[4][4];
            #pragma unroll
            for (int j = 0; j < 4; j++)
                #pragma unroll
                for (int q = 0; q < 4; q++) acc[j][q] = 0.f;

            #pragma unroll
            for (int kk = 0; kk < 4; kk++) {
                const int k0 = kk * 16 + tg * 2;
                unsigned ah[4], al[4];
                ah[0] = *(const unsigned*)&s->hhi[ row0      * KP + k0];
                ah[1] = *(const unsigned*)&s->hhi[(row0 + 8) * KP + k0];
                ah[2] = *(const unsigned*)&s->hhi[ row0      * KP + k0 + 8];
                ah[3] = *(const unsigned*)&s->hhi[(row0 + 8) * KP + k0 + 8];
                al[0] = *(const unsigned*)&s->hlo[ row0      * KP + k0];
                al[1] = *(const unsigned*)&s->hlo[(row0 + 8) * KP + k0];
                al[2] = *(const unsigned*)&s->hlo[ row0      * KP + k0 + 8];
                al[3] = *(const unsigned*)&s->hlo[(row0 + 8) * KP + k0 + 8];
                #pragma unroll
                for (int j = 0; j < 4; j++) {
                    const int col = nh * 32 + j * 8 + gID;
                    unsigned bh[2], blo[2];
                    bh[0]  = *(const unsigned*)&Whi[col * KP + k0];
                    bh[1]  = *(const unsigned*)&Whi[col * KP + k0 + 8];
                    blo[0] = *(const unsigned*)&Wlo[col * KP + k0];
                    blo[1] = *(const unsigned*)&Wlo[col * KP + k0 + 8];
                    mma16816(acc[j], ah, bh);
                    mma16816(acc[j], ah, blo);
                    mma16816(acc[j], al, bh);
                }
            }
            // epilogue: add bias, write fp32 rows (node-major, stride XP)
            #pragma unroll
            for (int j = 0; j < 4; j++) {
                const int col = nh * 32 + j * 8 + tg * 2;
                float2 bv = *reinterpret_cast<const float2*>(bias + col);
                int r0 = row0;           // gp = r>>5, node = r&31
                int r1 = row0 + 8;
                float2 v0 = make_float2(acc[j][0] + bv.x, acc[j][1] + bv.y);
                float2 v1 = make_float2(acc[j][2] + bv.x, acc[j][3] + bv.y);
                *reinterpret_cast<float2*>(dst + (size_t)(r0 >> 5) * (Nn * XP) + (r0 & 31) * XP + col) = v0;
                *reinterpret_cast<float2*>(dst + (size_t)(r1 >> 5) * (Nn * XP) + (r1 & 31) * XP + col) = v1;
            }
        }
        __syncthreads();

        // ---- edge scores per (gp, dst n, head, d-half); xr row cached in regs ----
        {
            const int hf = tid & 1;
            const int hd = (tid >> 1) & 3;
            const int n  = (tid >> 3) & 31;
            const int gp = tid >> 8;
            const int base = hd * Dd + hf * 8;
            float4 we0 = *reinterpret_cast<const float4*>(&s->Wes[base]);
            float4 we1 = *reinterpret_cast<const float4*>(&s->Wes[base + 4]);
            float4 at0 = *reinterpret_cast<const float4*>(&s->atts[base]);
            float4 at1 = *reinterpret_cast<const float4*>(&s->atts[base + 4]);
            float4 xr0 = *reinterpret_cast<const float4*>(&s->xr[gp][n * XP + base]);
            float4 xr1 = *reinterpret_cast<const float4*>(&s->xr[gp][n * XP + base + 4]);
            int dg = s->deg[n], o = s->off[n];
            for (int j = 0; j < dg; j++) {
                int e  = s->csr[o + j];
                int sr = s->srcs[e];
                float w = s->ew[e];
                float4 a0 = *reinterpret_cast<const float4*>(&s->xl[gp][sr * XP + base]);
                float4 a1 = *reinterpret_cast<const float4*>(&s->xl[gp][sr * XP + base + 4]);
                float z, sum = 0.f;
                z = a0.x + xr0.x + w * we0.x; z = (z > 0.f) ? z : 0.2f * z; sum += z * at0.x;
                z = a0.y + xr0.y + w * we0.y; z = (z > 0.f) ? z : 0.2f * z; sum += z * at0.y;
                z = a0.z + xr0.z + w * we0.z; z = (z > 0.f) ? z : 0.2f * z; sum += z * at0.z;
                z = a0.w + xr0.w + w * we0.w; z = (z > 0.f) ? z : 0.2f * z; sum += z * at0.w;
                z = a1.x + xr1.x + w * we1.x; z = (z > 0.f) ? z : 0.2f * z; sum += z * at1.x;
                z = a1.y + xr1.y + w * we1.y; z = (z > 0.f) ? z : 0.2f * z; sum += z * at1.y;
                z = a1.z + xr1.z + w * we1.z; z = (z > 0.f) ? z : 0.2f * z; sum += z * at1.z;
                z = a1.w + xr1.w + w * we1.w; z = (z > 0.f) ? z : 0.2f * z; sum += z * at1.w;
                s->sc[gp][e][hd * 2 + hf] = sum;
            }
        }
        __syncthreads();

        // ---- segment softmax: sum halves, exp in place (slot h*2), 1/denom ----
        if (tid < NG * Nn * Hh) {
            int gp = tid >> 7;
            int r  = tid & 127;
            int n  = r >> 2, hd = r & 3;
            int dg = s->deg[n], o = s->off[n];
            float m = -1e30f;
            for (int j = 0; j < dg; j++) {
                int e = s->csr[o + j];
                float2 p = *reinterpret_cast<const float2*>(&s->sc[gp][e][hd * 2]);
                m = fmaxf(m, p.x + p.y);
            }
            float den = 0.f;
            for (int j = 0; j < dg; j++) {
                int e = s->csr[o + j];
                float2 p = *reinterpret_cast<const float2*>(&s->sc[gp][e][hd * 2]);
                float ex = __expf(p.x + p.y - m);
                s->sc[gp][e][hd * 2] = ex;
                den += ex;
            }
            s->rden[gp][n][hd] = (dg > 0) ? (1.f / den) : 0.f;
        }
        __syncthreads();

        // ---- aggregate; layer0 -> relu -> bf16 hi/lo; layer1 -> fp32 hOut ----
        for (int t = tid; t < NG * Nn * Cc; t += NTHREADS) {
            int gp = t >> 11;
            int r  = t & 2047;
            int n  = r >> 6, c = r & 63;
            int hd2 = (c >> 4) << 1;
            int dg = s->deg[n], o = s->off[n];
            float a = 0.f;
            for (int j = 0; j < dg; j++) {
                int e = s->csr[o + j];
                a += s->sc[gp][e][hd2] * s->xl[gp][s->srcs[e] * XP + c];
            }
            a = a * s->rden[gp][n][hd2 >> 1] + s->bos[c];
            if (layer == 0) {
                a = fmaxf(a, 0.f);
                int oo = (gp * Nn + n) * KP + c;
                __nv_bfloat16 hi = __float2bfloat16(a);
                s->hhi[oo] = hi;
                s->hlo[oo] = __float2bfloat16(a - __bfloat162float(hi));
            } else {
                s->hOut[gp][n * OP + c] = a;
            }
        }
    }
    __syncthreads();

    // ---- write output: out[b,c,n,k,l0+l'] = hOut[l'][n*OP+c] ----
    float* ob = out + ((size_t)b * Cc * Nn) * (Kk * Ll) + (size_t)k * Ll + l0;
    for (int i2 = tid; i2 < Cc * Nn; i2 += NTHREADS) {
        int c = i2 >> 5, n = i2 & 31;
        float2 v = make_float2(s->hOut[0][n * OP + c], s->hOut[1][n * OP + c]);
        *reinterpret_cast<float2*>(ob + ((size_t)c * Nn + n) * (Kk * Ll)) = v;
    }
}

extern "C" void kernel_launch(void* const* d_in, const int* in_sizes, int n_in,
                              void* d_out, int out_size)
{
    const float* x   = (const float*)d_in[0];
    const int*   ei  = (const int*)  d_in[1];
    const float* ewg = (const float*)d_in[2];
    const float* Wl  = (const float*)d_in[3];
    const float* bl  = (const float*)d_in[4];
    const float* Wr  = (const float*)d_in[5];
    const float* br  = (const float*)d_in[6];
    const float* We  = (const float*)d_in[7];
    const float* att = (const float*)d_in[8];
    const float* bo  = (const float*)d_in[9];
    float* out = (float*)d_out;

    (void)in_sizes; (void)n_in; (void)out_size;

    int smem = (int)sizeof(Smem);
    cudaFuncSetAttribute(gat_fused, cudaFuncAttributeMaxDynamicSharedMemorySize, smem);

    dim3 grid(Bb * Kk * (Ll / NG));   // 3072 blocks, 2 graphs each
    gat_fused<<<grid, NTHREADS, smem>>>(x, ei, ewg, Wl, bl, Wr, br, We, att, bo, out);
}

// round 5
// speedup vs baseline: 1.7850x; 1.2312x over previous
#include <cuda_runtime.h>
#include <cuda_bf16.h>

// SpatialGNN: 2-layer GATv2, G = 6144 graphs, N=32, C=64, H=4, D=16, E=160.
// R5: setup kernel precomputes bf16 hi/lo weights (final smem layout), packed
// CSR (e, src*XP, ew) and per-layer vectors into __device__ globals; main
// kernel stages via bulk uint4 copies. Softmax fused into edge phase via
// pair-lane shuffle (inline max), one barrier fewer per layer.

#define Bb 16
#define Cc 64
#define Nn 32
#define Kk 16
#define Ll 24
#define Ee 160
#define Hh 4
#define Dd 16
#define NG 2
#define Mm 64         // GEMM rows = NG * Nn
#define KP 72         // bf16 row stride for h and weight tiles
#define XP 68         // fp32 row stride for xl/xr
#define OP 65         // fp32 row stride for hOut
#define NTHREADS 512

// ---- block-invariant precomputed state ----
__device__ __align__(16) __nv_bfloat16 g_w[2][2][2][Cc * KP]; // [layer][hi/lo][mat][co*KP+ci]
__device__ __align__(16) float g_vec[2][5 * Cc];              // [layer][bl|br|We|att|bo]
__device__ __align__(16) int4  g_csr[Ee];                     // {e, src*XP, ew_bits, 0}
__device__ int g_deg[Nn], g_off[Nn];

struct __align__(16) Smem {
    __nv_bfloat16 hhi[Mm * KP];
    __nv_bfloat16 hlo[Mm * KP];
    union {
        __nv_bfloat16 w[2][2][Cc * KP];   // [hi/lo][mat]
        float hOut[NG][Nn * OP];          // final-layer fp32 result (aliased)
    };
    float xl[NG][Nn * XP];
    float xr[NG][Nn * XP];
    float sc[NG][Ee][Hh];                 // full score -> exp in place
    float rden[NG][Nn][Hh];
    float vecs[5 * Cc] __attribute__((aligned(16)));
    int4  csrPack[Ee];
    int   deg[Nn], off[Nn];
};

__global__ void __launch_bounds__(NTHREADS)
gat_setup(const int* __restrict__ ei, const float* __restrict__ ewg,
          const float* __restrict__ Wl, const float* __restrict__ blg,
          const float* __restrict__ Wr, const float* __restrict__ brg,
          const float* __restrict__ Weg, const float* __restrict__ attg,
          const float* __restrict__ bog)
{
    __shared__ int sdst[Ee], ssrc[Ee];
    __shared__ float sew[Ee];
    __shared__ int sdeg[Nn], soff[Nn];
    const int tid = threadIdx.x;

    // weights -> bf16 hi/lo in final layout
    for (int t = tid; t < 2 * 2 * Cc * Cc; t += NTHREADS) {
        int layer = t >> 13, mat = (t >> 12) & 1, co = (t >> 6) & 63, ci = t & 63;
        const float* W = (mat ? Wr : Wl) + layer * Cc * Cc;
        float wv = W[co * Cc + ci];
        __nv_bfloat16 hi = __float2bfloat16(wv);
        g_w[layer][0][mat][co * KP + ci] = hi;
        g_w[layer][1][mat][co * KP + ci] = __float2bfloat16(wv - __bfloat162float(hi));
    }
    // per-layer vectors
    for (int t = tid; t < 2 * 5 * Cc; t += NTHREADS) {
        int layer = t / (5 * Cc), r = t % (5 * Cc), j = r >> 6, c = r & 63;
        const float* p = (j == 0) ? blg : (j == 1) ? brg : (j == 2) ? Weg : (j == 3) ? attg : bog;
        g_vec[layer][r] = p[layer * Cc + c];
    }
    // packed CSR
    if (tid < Ee) { ssrc[tid] = ei[tid]; sdst[tid] = ei[Ee + tid]; sew[tid] = ewg[tid]; }
    if (tid < Nn) sdeg[tid] = 0;
    __syncthreads();
    if (tid < Ee) atomicAdd(&sdeg[sdst[tid]], 1);
    __syncthreads();
    if (tid == 0) {
        int a = 0;
        for (int n = 0; n < Nn; n++) { soff[n] = a; g_off[n] = a; g_deg[n] = sdeg[n]; a += sdeg[n]; }
    }
    __syncthreads();
    if (tid < Ee) {
        int n = sdst[tid], rank = 0;
        for (int e2 = 0; e2 < tid; e2++) rank += (sdst[e2] == n);
        g_csr[soff[n] + rank] = make_int4(tid, ssrc[tid] * XP, __float_as_int(sew[tid]), 0);
    }
}

__device__ __forceinline__ void mma16816(float* d, const unsigned* a, const unsigned* b) {
    asm volatile(
        "mma.sync.aligned.m16n8k16.row.col.f32.bf16.bf16.f32 "
        "{%0,%1,%2,%3}, {%4,%5,%6,%7}, {%8,%9}, {%0,%1,%2,%3};"
        : "+f"(d[0]), "+f"(d[1]), "+f"(d[2]), "+f"(d[3])
        : "r"(a[0]), "r"(a[1]), "r"(a[2]), "r"(a[3]), "r"(b[0]), "r"(b[1]));
}

__global__ void __launch_bounds__(NTHREADS, 2)
gat_fused(const float* __restrict__ x, float* __restrict__ out)
{
    extern __shared__ char smem_raw[];
    Smem* s = reinterpret_cast<Smem*>(smem_raw);
    const int tid = threadIdx.x;
    const int bk = blockIdx.x / (Ll / NG);
    const int lg = blockIdx.x % (Ll / NG);
    const int b  = bk >> 4;
    const int k  = bk & 15;
    const int l0 = lg * NG;

    // ---- load h and convert to bf16 hi/lo ----
    const float* xb = x + ((size_t)b * Cc * Nn) * (Kk * Ll) + (size_t)k * Ll + l0;
    for (int i2 = tid; i2 < Cc * Nn; i2 += NTHREADS) {
        int c = i2 >> 5, n = i2 & 31;
        float2 v = *reinterpret_cast<const float2*>(xb + ((size_t)c * Nn + n) * (Kk * Ll));
        float vv[2] = {v.x, v.y};
        #pragma unroll
        for (int gp = 0; gp < NG; gp++) {
            int o = (gp * Nn + n) * KP + c;
            __nv_bfloat16 hi = __float2bfloat16(vv[gp]);
            s->hhi[o] = hi;
            s->hlo[o] = __float2bfloat16(vv[gp] - __bfloat162float(hi));
        }
    }
    // ---- topology copy (precomputed) ----
    for (int e = tid; e < Ee; e += NTHREADS) s->csrPack[e] = g_csr[e];
    if (tid < Nn) { s->deg[tid] = g_deg[tid]; s->off[tid] = g_off[tid]; }

    for (int layer = 0; layer < 2; layer++) {
        __syncthreads();

        // ---- stage weights: bulk contiguous copy ----
        {
            const uint4* wsrc = reinterpret_cast<const uint4*>(g_w[layer]);
            uint4* wdst = reinterpret_cast<uint4*>(s->w);
            #pragma unroll
            for (int t = tid; t < (2 * 2 * Cc * KP * 2) / 16; t += NTHREADS)
                wdst[t] = wsrc[t];
            if (tid < 5 * Cc) s->vecs[tid] = g_vec[layer][tid];
        }
        __syncthreads();

        // ---- tensor-core GEMM (bf16 hi/lo: hi*Whi + hi*Wlo + lo*Whi) ----
        {
            const int w    = tid >> 5;
            const int lane = tid & 31;
            const int gID  = lane >> 2;
            const int tg   = lane & 3;
            const int mat  = w >> 3;           // 0 -> xl, 1 -> xr
            const int mt   = (w >> 1) & 3;
            const int nh   = w & 1;
            const int row0 = mt * 16 + gID;
            const __nv_bfloat16* Whi = s->w[0][mat];
            const __nv_bfloat16* Wlo = s->w[1][mat];
            const float* bias = s->vecs + mat * Cc;
            float* dst        = mat ? (float*)s->xr : (float*)s->xl;

            float acc[4][4];
            #pragma unroll
            for (int j = 0; j < 4; j++)
                #pragma unroll
                for (int q = 0; q < 4; q++) acc[j][q] = 0.f;

            #pragma unroll
            for (int kk = 0; kk < 4; kk++) {
                const int k0 = kk * 16 + tg * 2;
                unsigned ah[4], al[4];
                ah[0] = *(const unsigned*)&s->hhi[ row0      * KP + k0];
                ah[1] = *(const unsigned*)&s->hhi[(row0 + 8) * KP + k0];
                ah[2] = *(const unsigned*)&s->hhi[ row0      * KP + k0 + 8];
                ah[3] = *(const unsigned*)&s->hhi[(row0 + 8) * KP + k0 + 8];
                al[0] = *(const unsigned*)&s->hlo[ row0      * KP + k0];
                al[1] = *(const unsigned*)&s->hlo[(row0 + 8) * KP + k0];
                al[2] = *(const unsigned*)&s->hlo[ row0      * KP + k0 + 8];
                al[3] = *(const unsigned*)&s->hlo[(row0 + 8) * KP + k0 + 8];
                #pragma unroll
                for (int j = 0; j < 4; j++) {
                    const int col = nh * 32 + j * 8 + gID;
                    unsigned bh[2], blo[2];
                    bh[0]  = *(const unsigned*)&Whi[col * KP + k0];
                    bh[1]  = *(const unsigned*)&Whi[col * KP + k0 + 8];
                    blo[0] = *(const unsigned*)&Wlo[col * KP + k0];
                    blo[1] = *(const unsigned*)&Wlo[col * KP + k0 + 8];
                    mma16816(acc[j], ah, bh);
                    mma16816(acc[j], ah, blo);
                    mma16816(acc[j], al, bh);
                }
            }
            #pragma unroll
            for (int j = 0; j < 4; j++) {
                const int col = nh * 32 + j * 8 + tg * 2;
                float2 bv = *reinterpret_cast<const float2*>(bias + col);
                int r0 = row0, r1 = row0 + 8;
                float2 v0 = make_float2(acc[j][0] + bv.x, acc[j][1] + bv.y);
                float2 v1 = make_float2(acc[j][2] + bv.x, acc[j][3] + bv.y);
                *reinterpret_cast<float2*>(dst + (size_t)(r0 >> 5) * (Nn * XP) + (r0 & 31) * XP + col) = v0;
                *reinterpret_cast<float2*>(dst + (size_t)(r1 >> 5) * (Nn * XP) + (r1 & 31) * XP + col) = v1;
            }
        }
        __syncthreads();

        // ---- edge scores + fused softmax ----
        {
            const int lane = tid & 31;
            const int hf = tid & 1;
            const int hd = (tid >> 1) & 3;
            const int n  = (tid >> 3) & 31;
            const int gp = tid >> 8;
            const int base = hd * Dd + hf * 8;
            const float* Wes  = s->vecs + 2 * Cc;
            const float* atts = s->vecs + 3 * Cc;
            float4 we0 = *reinterpret_cast<const float4*>(Wes + base);
            float4 we1 = *reinterpret_cast<const float4*>(Wes + base + 4);
            float4 at0 = *reinterpret_cast<const float4*>(atts + base);
            float4 at1 = *reinterpret_cast<const float4*>(atts + base + 4);
            float4 xr0 = *reinterpret_cast<const float4*>(&s->xr[gp][n * XP + base]);
            float4 xr1 = *reinterpret_cast<const float4*>(&s->xr[gp][n * XP + base + 4]);
            const int dg = s->deg[n], o = s->off[n];
            const unsigned pmask = 3u << (lane & 30);
            float m = -1e30f;
            for (int j = 0; j < dg; j++) {
                int4 ce = s->csrPack[o + j];
                float w = __int_as_float(ce.z);
                const float* xlp = &s->xl[gp][ce.y];
                float4 a0 = *reinterpret_cast<const float4*>(xlp + base);
                float4 a1 = *reinterpret_cast<const float4*>(xlp + base + 4);
                float z, sum = 0.f;
                z = a0.x + xr0.x + w * we0.x; z = (z > 0.f) ? z : 0.2f * z; sum += z * at0.x;
                z = a0.y + xr0.y + w * we0.y; z = (z > 0.f) ? z : 0.2f * z; sum += z * at0.y;
                z = a0.z + xr0.z + w * we0.z; z = (z > 0.f) ? z : 0.2f * z; sum += z * at0.z;
                z = a0.w + xr0.w + w * we0.w; z = (z > 0.f) ? z : 0.2f * z; sum += z * at0.w;
                z = a1.x + xr1.x + w * we1.x; z = (z > 0.f) ? z : 0.2f * z; sum += z * at1.x;
                z = a1.y + xr1.y + w * we1.y; z = (z > 0.f) ? z : 0.2f * z; sum += z * at1.y;
                z = a1.z + xr1.z + w * we1.z; z = (z > 0.f) ? z : 0.2f * z; sum += z * at1.z;
                z = a1.w + xr1.w + w * we1.w; z = (z > 0.f) ? z : 0.2f * z; sum += z * at1.w;
                float full = sum + __shfl_xor_sync(pmask, sum, 1);
                if (hf == 0) s->sc[gp][ce.x][hd] = full;
                m = fmaxf(m, full);
            }
            if (hf == 0) {
                float den = 0.f;
                for (int j = 0; j < dg; j++) {
                    int e = s->csrPack[o + j].x;
                    float ex = __expf(s->sc[gp][e][hd] - m);
                    s->sc[gp][e][hd] = ex;
                    den += ex;
                }
                s->rden[gp][n][hd] = (dg > 0) ? (1.f / den) : 0.f;
            }
        }
        __syncthreads();

        // ---- aggregate; layer0 -> relu -> bf16 hi/lo; layer1 -> fp32 hOut ----
        for (int t = tid; t < NG * Nn * Cc; t += NTHREADS) {
            int gp = t >> 11;
            int r  = t & 2047;
            int n  = r >> 6, c = r & 63;
            int hd = c >> 4;
            int dg = s->deg[n], o = s->off[n];
            float a = 0.f;
            for (int j = 0; j < dg; j++) {
                int4 ce = s->csrPack[o + j];
                a += s->sc[gp][ce.x][hd] * s->xl[gp][ce.y + c];
            }
            a = a * s->rden[gp][n][hd] + s->vecs[4 * Cc + c];
            if (layer == 0) {
                a = fmaxf(a, 0.f);
                int oo = (gp * Nn + n) * KP + c;
                __nv_bfloat16 hi = __float2bfloat16(a);
                s->hhi[oo] = hi;
                s->hlo[oo] = __float2bfloat16(a - __bfloat162float(hi));
            } else {
                s->hOut[gp][n * OP + c] = a;
            }
        }
    }
    __syncthreads();

    // ---- write output ----
    float* ob = out + ((size_t)b * Cc * Nn) * (Kk * Ll) + (size_t)k * Ll + l0;
    for (int i2 = tid; i2 < Cc * Nn; i2 += NTHREADS) {
        int c = i2 >> 5, n = i2 & 31;
        float2 v = make_float2(s->hOut[0][n * OP + c], s->hOut[1][n * OP + c]);
        *reinterpret_cast<float2*>(ob + ((size_t)c * Nn + n) * (Kk * Ll)) = v;
    }
}

extern "C" void kernel_launch(void* const* d_in, const int* in_sizes, int n_in,
                              void* d_out, int out_size)
{
    const float* x   = (const float*)d_in[0];
    const int*   ei  = (const int*)  d_in[1];
    const float* ewg = (const float*)d_in[2];
    const float* Wl  = (const float*)d_in[3];
    const float* bl  = (const float*)d_in[4];
    const float* Wr  = (const float*)d_in[5];
    const float* br  = (const float*)d_in[6];
    const float* We  = (const float*)d_in[7];
    const float* att = (const float*)d_in[8];
    const float* bo  = (const float*)d_in[9];
    float* out = (float*)d_out;

    (void)in_sizes; (void)n_in; (void)out_size;

    gat_setup<<<1, NTHREADS>>>(ei, ewg, Wl, bl, Wr, br, We, att, bo);

    int smem = (int)sizeof(Smem);
    cudaFuncSetAttribute(gat_fused, cudaFuncAttributeMaxDynamicSharedMemorySize, smem);
    dim3 grid(Bb * Kk * (Ll / NG));   // 3072 blocks, 2 graphs each
    gat_fused<<<grid, NTHREADS, smem>>>(x, out);
}

// round 6
// speedup vs baseline: 2.0475x; 1.1470x over previous
#include <cuda_runtime.h>
#include <cuda_bf16.h>

// SpatialGNN: 2-layer GATv2, G = 6144 graphs, N=32, C=64, H=4, D=16, E=160.
// R6: ldmatrix.x4 fragment loads for the bf16 hi/lo tensor-core GEMM (24 LDSM
// vs 96 LDS.32 per warp) and float4 aggregation handling both graphs per
// deg-loop iteration (4x fewer gather LDS instructions).

#define Bb 16
#define Cc 64
#define Nn 32
#define Kk 16
#define Ll 24
#define Ee 160
#define Hh 4
#define Dd 16
#define NG 2
#define Mm 64         // GEMM rows = NG * Nn
#define KP 72         // bf16 row stride for h and weight tiles
#define XP 68         // fp32 row stride for xl/xr
#define OP 68         // fp32 row stride for hOut (16B-aligned rows)
#define NTHREADS 512

// ---- block-invariant precomputed state ----
__device__ __align__(16) __nv_bfloat16 g_w[2][2][2][Cc * KP]; // [layer][hi/lo][mat][co*KP+ci]
__device__ __align__(16) float g_vec[2][5 * Cc];              // [layer][bl|br|We|att|bo]
__device__ __align__(16) int4  g_csr[Ee];                     // {e, src*XP, ew_bits, 0}
__device__ int g_deg[Nn], g_off[Nn];

struct __align__(16) Smem {
    __nv_bfloat16 hhi[Mm * KP];
    __nv_bfloat16 hlo[Mm * KP];
    union {
        __nv_bfloat16 w[2][2][Cc * KP];   // [hi/lo][mat]
        float hOut[NG][Nn * OP];          // final-layer fp32 result (aliased)
    };
    float xl[NG][Nn * XP];
    float xr[NG][Nn * XP];
    float sc[NG][Ee][Hh];                 // full score -> exp in place
    float rden[NG][Nn][Hh];
    float vecs[5 * Cc] __attribute__((aligned(16)));
    int4  csrPack[Ee];
    int   deg[Nn], off[Nn];
};

__global__ void __launch_bounds__(NTHREADS)
gat_setup(const int* __restrict__ ei, const float* __restrict__ ewg,
          const float* __restrict__ Wl, const float* __restrict__ blg,
          const float* __restrict__ Wr, const float* __restrict__ brg,
          const float* __restrict__ Weg, const float* __restrict__ attg,
          const float* __restrict__ bog)
{
    __shared__ int sdst[Ee], ssrc[Ee];
    __shared__ float sew[Ee];
    __shared__ int sdeg[Nn], soff[Nn];
    const int tid = threadIdx.x;

    for (int t = tid; t < 2 * 2 * Cc * Cc; t += NTHREADS) {
        int layer = t >> 13, mat = (t >> 12) & 1, co = (t >> 6) & 63, ci = t & 63;
        const float* W = (mat ? Wr : Wl) + layer * Cc * Cc;
        float wv = W[co * Cc + ci];
        __nv_bfloat16 hi = __float2bfloat16(wv);
        g_w[layer][0][mat][co * KP + ci] = hi;
        g_w[layer][1][mat][co * KP + ci] = __float2bfloat16(wv - __bfloat162float(hi));
    }
    for (int t = tid; t < 2 * 5 * Cc; t += NTHREADS) {
        int layer = t / (5 * Cc), r = t % (5 * Cc), j = r >> 6, c = r & 63;
        const float* p = (j == 0) ? blg : (j == 1) ? brg : (j == 2) ? Weg : (j == 3) ? attg : bog;
        g_vec[layer][r] = p[layer * Cc + c];
    }
    if (tid < Ee) { ssrc[tid] = ei[tid]; sdst[tid] = ei[Ee + tid]; sew[tid] = ewg[tid]; }
    if (tid < Nn) sdeg[tid] = 0;
    __syncthreads();
    if (tid < Ee) atomicAdd(&sdeg[sdst[tid]], 1);
    __syncthreads();
    if (tid == 0) {
        int a = 0;
        for (int n = 0; n < Nn; n++) { soff[n] = a; g_off[n] = a; g_deg[n] = sdeg[n]; a += sdeg[n]; }
    }
    __syncthreads();
    if (tid < Ee) {
        int n = sdst[tid], rank = 0;
        for (int e2 = 0; e2 < tid; e2++) rank += (sdst[e2] == n);
        g_csr[soff[n] + rank] = make_int4(tid, ssrc[tid] * XP, __float_as_int(sew[tid]), 0);
    }
}

__device__ __forceinline__ void mma16816(float* d, const unsigned* a, const unsigned* b) {
    asm volatile(
        "mma.sync.aligned.m16n8k16.row.col.f32.bf16.bf16.f32 "
        "{%0,%1,%2,%3}, {%4,%5,%6,%7}, {%8,%9}, {%0,%1,%2,%3};"
        : "+f"(d[0]), "+f"(d[1]), "+f"(d[2]), "+f"(d[3])
        : "r"(a[0]), "r"(a[1]), "r"(a[2]), "r"(a[3]), "r"(b[0]), "r"(b[1]));
}

__device__ __forceinline__ void ldsm_x4(unsigned* r, unsigned addr) {
    asm volatile("ldmatrix.sync.aligned.m8n8.x4.shared.b16 {%0,%1,%2,%3}, [%4];"
        : "=r"(r[0]), "=r"(r[1]), "=r"(r[2]), "=r"(r[3]) : "r"(addr));
}

__device__ __forceinline__ unsigned cvta_s(const void* p) {
    return (unsigned)__cvta_generic_to_shared(p);
}

__global__ void __launch_bounds__(NTHREADS, 2)
gat_fused(const float* __restrict__ x, float* __restrict__ out)
{
    extern __shared__ char smem_raw[];
    Smem* s = reinterpret_cast<Smem*>(smem_raw);
    const int tid = threadIdx.x;
    const int bk = blockIdx.x / (Ll / NG);
    const int lg = blockIdx.x % (Ll / NG);
    const int b  = bk >> 4;
    const int k  = bk & 15;
    const int l0 = lg * NG;

    // ---- load h and convert to bf16 hi/lo ----
    const float* xb = x + ((size_t)b * Cc * Nn) * (Kk * Ll) + (size_t)k * Ll + l0;
    for (int i2 = tid; i2 < Cc * Nn; i2 += NTHREADS) {
        int c = i2 >> 5, n = i2 & 31;
        float2 v = *reinterpret_cast<const float2*>(xb + ((size_t)c * Nn + n) * (Kk * Ll));
        float vv[2] = {v.x, v.y};
        #pragma unroll
        for (int gp = 0; gp < NG; gp++) {
            int o = (gp * Nn + n) * KP + c;
            __nv_bfloat16 hi = __float2bfloat16(vv[gp]);
            s->hhi[o] = hi;
            s->hlo[o] = __float2bfloat16(vv[gp] - __bfloat162float(hi));
        }
    }
    for (int e = tid; e < Ee; e += NTHREADS) s->csrPack[e] = g_csr[e];
    if (tid < Nn) { s->deg[tid] = g_deg[tid]; s->off[tid] = g_off[tid]; }

    for (int layer = 0; layer < 2; layer++) {
        __syncthreads();

        // ---- stage weights: bulk contiguous copy ----
        {
            const uint4* wsrc = reinterpret_cast<const uint4*>(g_w[layer]);
            uint4* wdst = reinterpret_cast<uint4*>(s->w);
            #pragma unroll
            for (int t = tid; t < (2 * 2 * Cc * KP * 2) / 16; t += NTHREADS)
                wdst[t] = wsrc[t];
            if (tid < 5 * Cc) s->vecs[tid] = g_vec[layer][tid];
        }
        __syncthreads();

        // ---- tensor-core GEMM via ldmatrix (hi*Whi + hi*Wlo + lo*Whi) ----
        {
            const int w    = tid >> 5;
            const int lane = tid & 31;
            const int gID  = lane >> 2;
            const int tg   = lane & 3;
            const int mat  = w >> 3;           // 0 -> xl, 1 -> xr
            const int mt   = (w >> 1) & 3;
            const int nh   = w & 1;
            const int lr   = lane & 7;
            const int seg  = lane >> 3;
            // A tile lane address components (16x16 block at rows mt*16, k kk*16)
            const int rowA  = mt * 16 + (seg & 1) * 8 + lr;
            const int kOffA = (seg >> 1) * 8;
            // B tile lane address components (16 cols starting nh*32 + jp*16)
            const int colB0 = nh * 32 + (seg >> 1) * 8 + lr;
            const int kOffB = (seg & 1) * 8;

            const unsigned hhiB = cvta_s(s->hhi);
            const unsigned hloB = cvta_s(s->hlo);
            const unsigned whiB = cvta_s(s->w[0][mat]);
            const unsigned wloB = cvta_s(s->w[1][mat]);
            const float* bias = s->vecs + mat * Cc;
            float* dst        = mat ? (float*)s->xr : (float*)s->xl;

            float acc[4][4];
            #pragma unroll
            for (int j = 0; j < 4; j++)
                #pragma unroll
                for (int q = 0; q < 4; q++) acc[j][q] = 0.f;

            #pragma unroll
            for (int kk = 0; kk < 4; kk++) {
                const int ka = kk * 16;
                unsigned ah[4], al[4];
                ldsm_x4(ah, hhiB + (unsigned)(rowA * KP + ka + kOffA) * 2);
                ldsm_x4(al, hloB + (unsigned)(rowA * KP + ka + kOffA) * 2);
                #pragma unroll
                for (int jp = 0; jp < 2; jp++) {
                    const int cB = colB0 + jp * 16;
                    unsigned bh[4], blo[4];
                    ldsm_x4(bh,  whiB + (unsigned)(cB * KP + ka + kOffB) * 2);
                    ldsm_x4(blo, wloB + (unsigned)(cB * KP + ka + kOffB) * 2);
                    mma16816(acc[jp * 2],     ah, bh);
                    mma16816(acc[jp * 2],     ah, blo);
                    mma16816(acc[jp * 2],     al, bh);
                    mma16816(acc[jp * 2 + 1], ah, bh + 2);
                    mma16816(acc[jp * 2 + 1], ah, blo + 2);
                    mma16816(acc[jp * 2 + 1], al, bh + 2);
                }
            }
            #pragma unroll
            for (int j = 0; j < 4; j++) {
                const int col = nh * 32 + j * 8 + tg * 2;
                float2 bv = *reinterpret_cast<const float2*>(bias + col);
                int r0 = mt * 16 + gID, r1 = r0 + 8;
                float2 v0 = make_float2(acc[j][0] + bv.x, acc[j][1] + bv.y);
                float2 v1 = make_float2(acc[j][2] + bv.x, acc[j][3] + bv.y);
                *reinterpret_cast<float2*>(dst + (size_t)(r0 >> 5) * (Nn * XP) + (r0 & 31) * XP + col) = v0;
                *reinterpret_cast<float2*>(dst + (size_t)(r1 >> 5) * (Nn * XP) + (r1 & 31) * XP + col) = v1;
            }
        }
        __syncthreads();

        // ---- edge scores + fused softmax ----
        {
            const int lane = tid & 31;
            const int hf = tid & 1;
            const int hd = (tid >> 1) & 3;
            const int n  = (tid >> 3) & 31;
            const int gp = tid >> 8;
            const int base = hd * Dd + hf * 8;
            const float* Wes  = s->vecs + 2 * Cc;
            const float* atts = s->vecs + 3 * Cc;
            float4 we0 = *reinterpret_cast<const float4*>(Wes + base);
            float4 we1 = *reinterpret_cast<const float4*>(Wes + base + 4);
            float4 at0 = *reinterpret_cast<const float4*>(atts + base);
            float4 at1 = *reinterpret_cast<const float4*>(atts + base + 4);
            float4 xr0 = *reinterpret_cast<const float4*>(&s->xr[gp][n * XP + base]);
            float4 xr1 = *reinterpret_cast<const float4*>(&s->xr[gp][n * XP + base + 4]);
            const int dg = s->deg[n], o = s->off[n];
            const unsigned pmask = 3u << (lane & 30);
            float m = -1e30f;
            for (int j = 0; j < dg; j++) {
                int4 ce = s->csrPack[o + j];
                float w = __int_as_float(ce.z);
                const float* xlp = &s->xl[gp][ce.y];
                float4 a0 = *reinterpret_cast<const float4*>(xlp + base);
                float4 a1 = *reinterpret_cast<const float4*>(xlp + base + 4);
                float z, sum = 0.f;
                z = a0.x + xr0.x + w * we0.x; z = (z > 0.f) ? z : 0.2f * z; sum += z * at0.x;
                z = a0.y + xr0.y + w * we0.y; z = (z > 0.f) ? z : 0.2f * z; sum += z * at0.y;
                z = a0.z + xr0.z + w * we0.z; z = (z > 0.f) ? z : 0.2f * z; sum += z * at0.z;
                z = a0.w + xr0.w + w * we0.w; z = (z > 0.f) ? z : 0.2f * z; sum += z * at0.w;
                z = a1.x + xr1.x + w * we1.x; z = (z > 0.f) ? z : 0.2f * z; sum += z * at1.x;
                z = a1.y + xr1.y + w * we1.y; z = (z > 0.f) ? z : 0.2f * z; sum += z * at1.y;
                z = a1.z + xr1.z + w * we1.z; z = (z > 0.f) ? z : 0.2f * z; sum += z * at1.z;
                z = a1.w + xr1.w + w * we1.w; z = (z > 0.f) ? z : 0.2f * z; sum += z * at1.w;
                float full = sum + __shfl_xor_sync(pmask, sum, 1);
                if (hf == 0) s->sc[gp][ce.x][hd] = full;
                m = fmaxf(m, full);
            }
            if (hf == 0) {
                float den = 0.f;
                for (int j = 0; j < dg; j++) {
                    int e = s->csrPack[o + j].x;
                    float ex = __expf(s->sc[gp][e][hd] - m);
                    s->sc[gp][e][hd] = ex;
                    den += ex;
                }
                s->rden[gp][n][hd] = (dg > 0) ? (1.f / den) : 0.f;
            }
        }
        __syncthreads();

        // ---- aggregate (float4 over channels; both graphs per deg iteration) ----
        {
            const int c4 = tid & 15;          // 4-channel group 0..15
            const int n  = tid >> 4;          // node 0..31
            const int hd = c4 >> 2;
            const int cb = c4 * 4;
            const int dg = s->deg[n], o = s->off[n];
            float4 a0 = make_float4(0.f, 0.f, 0.f, 0.f);
            float4 a1 = make_float4(0.f, 0.f, 0.f, 0.f);
            for (int j = 0; j < dg; j++) {
                int4 ce = s->csrPack[o + j];
                float s0 = s->sc[0][ce.x][hd];
                float s1 = s->sc[1][ce.x][hd];
                float4 v0 = *reinterpret_cast<const float4*>(&s->xl[0][ce.y + cb]);
                float4 v1 = *reinterpret_cast<const float4*>(&s->xl[1][ce.y + cb]);
                a0.x = fmaf(s0, v0.x, a0.x); a0.y = fmaf(s0, v0.y, a0.y);
                a0.z = fmaf(s0, v0.z, a0.z); a0.w = fmaf(s0, v0.w, a0.w);
                a1.x = fmaf(s1, v1.x, a1.x); a1.y = fmaf(s1, v1.y, a1.y);
                a1.z = fmaf(s1, v1.z, a1.z); a1.w = fmaf(s1, v1.w, a1.w);
            }
            float r0 = s->rden[0][n][hd], r1 = s->rden[1][n][hd];
            float4 bo4 = *reinterpret_cast<const float4*>(s->vecs + 4 * Cc + cb);
            a0.x = fmaf(a0.x, r0, bo4.x); a0.y = fmaf(a0.y, r0, bo4.y);
            a0.z = fmaf(a0.z, r0, bo4.z); a0.w = fmaf(a0.w, r0, bo4.w);
            a1.x = fmaf(a1.x, r1, bo4.x); a1.y = fmaf(a1.y, r1, bo4.y);
            a1.z = fmaf(a1.z, r1, bo4.z); a1.w = fmaf(a1.w, r1, bo4.w);
            if (layer == 0) {
                float v0[4] = {fmaxf(a0.x, 0.f), fmaxf(a0.y, 0.f), fmaxf(a0.z, 0.f), fmaxf(a0.w, 0.f)};
                float v1[4] = {fmaxf(a1.x, 0.f), fmaxf(a1.y, 0.f), fmaxf(a1.z, 0.f), fmaxf(a1.w, 0.f)};
                int o0 = n * KP + cb, o1 = (Nn + n) * KP + cb;
                #pragma unroll
                for (int q = 0; q < 4; q++) {
                    __nv_bfloat16 h0 = __float2bfloat16(v0[q]);
                    __nv_bfloat16 h1 = __float2bfloat16(v1[q]);
                    s->hhi[o0 + q] = h0;
                    s->hlo[o0 + q] = __float2bfloat16(v0[q] - __bfloat162float(h0));
                    s->hhi[o1 + q] = h1;
                    s->hlo[o1 + q] = __float2bfloat16(v1[q] - __bfloat162float(h1));
                }
            } else {
                *reinterpret_cast<float4*>(&s->hOut[0][n * OP + cb]) = a0;
                *reinterpret_cast<float4*>(&s->hOut[1][n * OP + cb]) = a1;
            }
        }
    }
    __syncthreads();

    // ---- write output ----
    float* ob = out + ((size_t)b * Cc * Nn) * (Kk * Ll) + (size_t)k * Ll + l0;
    for (int i2 = tid; i2 < Cc * Nn; i2 += NTHREADS) {
        int c = i2 >> 5, n = i2 & 31;
        float2 v = make_float2(s->hOut[0][n * OP + c], s->hOut[1][n * OP + c]);
        *reinterpret_cast<float2*>(ob + ((size_t)c * Nn + n) * (Kk * Ll)) = v;
    }
}

extern "C" void kernel_launch(void* const* d_in, const int* in_sizes, int n_in,
                              void* d_out, int out_size)
{
    const float* x   = (const float*)d_in[0];
    const int*   ei  = (const int*)  d_in[1];
    const float* ewg = (const float*)d_in[2];
    const float* Wl  = (const float*)d_in[3];
    const float* bl  = (const float*)d_in[4];
    const float* Wr  = (const float*)d_in[5];
    const float* br  = (const float*)d_in[6];
    const float* We  = (const float*)d_in[7];
    const float* att = (const float*)d_in[8];
    const float* bo  = (const float*)d_in[9];
    float* out = (float*)d_out;

    (void)in_sizes; (void)n_in; (void)out_size;

    gat_setup<<<1, NTHREADS>>>(ei, ewg, Wl, bl, Wr, br, We, att, bo);

    int smem = (int)sizeof(Smem);
    cudaFuncSetAttribute(gat_fused, cudaFuncAttributeMaxDynamicSharedMemorySize, smem);
    dim3 grid(Bb * Kk * (Ll / NG));   // 3072 blocks, 2 graphs each
    gat_fused<<<grid, NTHREADS, smem>>>(x, out);
}